// round 9
// baseline (speedup 1.0000x reference)
#include <cuda_runtime.h>
#include <math.h>
#include <stdint.h>

#define BB   4
#define SS   512
#define DMM  768
#define LLN  2
#define DII  1536
#define DSS  16
#define KKC  4
#define DTRR 48
#define RTOT (BB*SS)         // 2048
#define DBCW (DTRR + 2*DSS)  // 80
#define XSPLIT 16            // split-K slices for xproj

// -------------------- scratch (device globals; no allocs) --------------------
__device__ __align__(256) float g_h    [RTOT*DMM];
__device__ __align__(256) float g_xln  [RTOT*DMM];
__device__ __align__(256) float g_xz   [RTOT*2*DII];
__device__ __align__(256) float g_xc   [RTOT*DII];
__device__ __align__(256) float g_dbc  [RTOT*DBCW];
__device__ __align__(256) float g_delta[RTOT*DII];
__device__ __align__(256) float g_y    [RTOT*DII];
__device__ __align__(256) float g_part [XSPLIT*RTOT*DBCW];
__device__ __align__(256) float g_rowdot[RTOT];

// -------------------- helpers --------------------
__device__ __forceinline__ void mma_tf32(float* c, const uint32_t* a, const uint32_t* b) {
    asm volatile(
        "mma.sync.aligned.m16n8k8.row.col.f32.tf32.tf32.f32 "
        "{%0,%1,%2,%3}, {%4,%5,%6,%7}, {%8,%9}, {%0,%1,%2,%3};"
        : "+f"(c[0]), "+f"(c[1]), "+f"(c[2]), "+f"(c[3])
        : "r"(a[0]), "r"(a[1]), "r"(a[2]), "r"(a[3]), "r"(b[0]), "r"(b[1]));
}
__device__ __forceinline__ void cp_async16(uint32_t smem_addr, const float* gptr) {
    asm volatile("cp.async.cg.shared.global [%0], [%1], 16;\n"
                 :: "r"(smem_addr), "l"(gptr));
}
__device__ __forceinline__ void cp_commit() {
    asm volatile("cp.async.commit_group;\n" ::: "memory");
}
template<int N>
__device__ __forceinline__ void cp_wait() {
    asm volatile("cp.async.wait_group %0;\n" :: "n"(N) : "memory");
}
__device__ __forceinline__ float gelu_exact(float v) {
    return 0.5f * v * (1.0f + erff(v * 0.70710678118654752f));
}

// -------------------- embed --------------------
__global__ void embed_kernel(const float* __restrict__ x, const float* __restrict__ w_in,
                             const float* __restrict__ b_in, const float* __restrict__ pe,
                             float* __restrict__ h) {
    int idx = blockIdx.x * blockDim.x + threadIdx.x;
    if (idx >= RTOT*DMM) return;
    int r = idx / DMM;
    int d = idx - r*DMM;
    int s = r & (SS-1);
    h[idx] = x[r]*w_in[d] + b_in[d] + pe[s*DMM + d];
}

// -------------------- layernorm --------------------
__global__ __launch_bounds__(256) void ln_kernel(const float* __restrict__ x,
                                                 const float* __restrict__ w,
                                                 const float* __restrict__ b,
                                                 float* __restrict__ y) {
    int row = blockIdx.x;
    const float* xr = x + (size_t)row*DMM;
    float v[3];
    float s = 0.f, sq = 0.f;
#pragma unroll
    for (int i = 0; i < 3; i++) {
        v[i] = xr[threadIdx.x + 256*i];
        s  += v[i];
        sq += v[i]*v[i];
    }
    __shared__ float sms[8], smq[8];
    __shared__ float mu_s, rs_s;
#pragma unroll
    for (int o = 16; o > 0; o >>= 1) {
        s  += __shfl_xor_sync(0xffffffffu, s,  o);
        sq += __shfl_xor_sync(0xffffffffu, sq, o);
    }
    int lane = threadIdx.x & 31, wid = threadIdx.x >> 5;
    if (lane == 0) { sms[wid] = s; smq[wid] = sq; }
    __syncthreads();
    if (threadIdx.x == 0) {
        float S = 0.f, Q = 0.f;
        for (int i = 0; i < 8; i++) { S += sms[i]; Q += smq[i]; }
        float mu = S * (1.0f/DMM);
        float var = Q * (1.0f/DMM) - mu*mu;
        mu_s = mu;
        rs_s = rsqrtf(var + 1e-5f);
    }
    __syncthreads();
    float mu = mu_s, rs = rs_s;
    float* yr = y + (size_t)row*DMM;
#pragma unroll
    for (int i = 0; i < 3; i++) {
        int d = threadIdx.x + 256*i;
        yr[d] = (v[i]-mu)*rs*w[d] + b[d];
    }
}

// -------------------- tensor-core tf32 GEMM, cp.async 4-stage, no-cvt (proven) ------
template<int BN, int ACT, bool HAS_BIAS, bool HAS_RES>
__global__ __launch_bounds__(256, 2) void gemm_tc(
    const float* __restrict__ A, int lda,
    const float* __restrict__ Bw, int ldb,     // (N, K) row-major
    const float* __restrict__ bias,
    const float* res,
    float* C, int ldc,
    int M, int N, int Kd)
{
    const int BM = 128, SK = 20, STG = 4;
    const int WC = (BN == 128) ? 4 : 2;
    const int WARP_M = (BN == 128) ? 64 : 32;
    const int MT = WARP_M / 16;
    const int NT = 4;

    extern __shared__ float sm[];
    float* As = sm;
    float* Bs = sm + STG*BM*SK;

    int tid  = threadIdx.x;
    int wid  = tid >> 5;
    int lane = tid & 31;
    int g    = lane >> 2;
    int tg   = lane & 3;
    int wm = (wid / WC) * WARP_M;
    int wn = (wid % WC) * 32;
    int m0 = blockIdx.y * BM;
    int n0 = blockIdx.x * BN;

    float acc[MT][NT][4];
#pragma unroll
    for (int i = 0; i < MT; i++)
#pragma unroll
        for (int j = 0; j < NT; j++)
#pragma unroll
            for (int q = 0; q < 4; q++) acc[i][j][q] = 0.f;

    auto stageLoad = [&](int k0, int buf) {
        float* Asb = As + buf*BM*SK;
        float* Bsb = Bs + buf*BN*SK;
#pragma unroll
        for (int q = 0; q < 2; q++) {
            int f = tid + q*256;
            int m = f >> 2, kv = (f & 3) * 4;
            cp_async16((uint32_t)__cvta_generic_to_shared(Asb + m*SK + kv),
                       A + (size_t)(m0+m)*lda + k0 + kv);
        }
#pragma unroll
        for (int q = 0; q < BN/64; q++) {
            int f = tid + q*256;
            int n = f >> 2, kv = (f & 3) * 4;
            cp_async16((uint32_t)__cvta_generic_to_shared(Bsb + n*SK + kv),
                       Bw + (size_t)(n0+n)*ldb + k0 + kv);
        }
    };

    int nIter = Kd / 16;
    stageLoad(0, 0);  cp_commit();
    stageLoad(16, 1); cp_commit();
    stageLoad(32, 2); cp_commit();

    for (int it = 0; it < nIter; it++) {
        cp_wait<2>();
        __syncthreads();

        int buf = it & 3;
        const float* Asb = As + buf*BM*SK;
        const float* Bsb = Bs + buf*BN*SK;
#pragma unroll
        for (int kk = 0; kk < 2; kk++) {
            int kb = kk*8;
            uint32_t bf[NT][2];
#pragma unroll
            for (int tn = 0; tn < NT; tn++) {
                int n = wn + tn*8 + g;
                bf[tn][0] = __float_as_uint(Bsb[n*SK + kb + tg]);
                bf[tn][1] = __float_as_uint(Bsb[n*SK + kb + tg + 4]);
            }
#pragma unroll
            for (int tm = 0; tm < MT; tm++) {
                int r = wm + tm*16 + g;
                uint32_t af[4];
                af[0] = __float_as_uint(Asb[(r    )*SK + kb + tg    ]);
                af[1] = __float_as_uint(Asb[(r + 8)*SK + kb + tg    ]);
                af[2] = __float_as_uint(Asb[(r    )*SK + kb + tg + 4]);
                af[3] = __float_as_uint(Asb[(r + 8)*SK + kb + tg + 4]);
#pragma unroll
                for (int tn = 0; tn < NT; tn++)
                    mma_tf32(acc[tm][tn], af, bf[tn]);
            }
        }

        int nxt = it + 3;
        if (nxt < nIter) stageLoad(nxt*16, nxt & 3);
        cp_commit();
    }

    // epilogue
#pragma unroll
    for (int tm = 0; tm < MT; tm++) {
        int mrow = m0 + wm + tm*16 + g;
#pragma unroll
        for (int tn = 0; tn < NT; tn++) {
            int ncol = n0 + wn + tn*8 + 2*tg;
            float b0v = 0.f, b1v = 0.f;
            if (HAS_BIAS) { b0v = bias[ncol]; b1v = bias[ncol+1]; }
            float v0 = acc[tm][tn][0] + b0v;
            float v1 = acc[tm][tn][1] + b1v;
            float v2 = acc[tm][tn][2] + b0v;
            float v3 = acc[tm][tn][3] + b1v;
            if (ACT == 1) {
                v0 = gelu_exact(v0); v1 = gelu_exact(v1);
                v2 = gelu_exact(v2); v3 = gelu_exact(v3);
            } else if (ACT == 2) {
                v0 = (v0 > 20.f) ? v0 : log1pf(__expf(v0));
                v1 = (v1 > 20.f) ? v1 : log1pf(__expf(v1));
                v2 = (v2 > 20.f) ? v2 : log1pf(__expf(v2));
                v3 = (v3 > 20.f) ? v3 : log1pf(__expf(v3));
            }
            size_t o0 = (size_t)mrow*ldc + ncol;
            size_t o1 = (size_t)(mrow+8)*ldc + ncol;
            if (HAS_RES) {
                float2 r0 = *reinterpret_cast<const float2*>(res + o0);
                float2 r1 = *reinterpret_cast<const float2*>(res + o1);
                v0 += r0.x; v1 += r0.y; v2 += r1.x; v3 += r1.y;
            }
            *reinterpret_cast<float2*>(C + o0) = make_float2(v0, v1);
            *reinterpret_cast<float2*>(C + o1) = make_float2(v2, v3);
        }
    }
}

// -------------------- fp32 SIMT GEMM (xproj split-K) --------------------
// NOTE: TN==8 B-fragment branch is REQUIRED for BN=128 (regression in R7/R8 caused NaN).
template<int BN, int ACT, bool HAS_BIAS, bool HAS_RES, bool SPLIT>
__global__ __launch_bounds__(256) void gemm2(
    const float* __restrict__ A, int lda,
    const float* __restrict__ Bw, int ldb,
    const float* __restrict__ bias,
    const float* res,
    float* C, int ldc,
    int M, int N, int Kd, int kSlice,
    float* part)
{
    const int BM = 128, BK = 8, TM = 8;
    const int TN = BN / 16;
    __shared__ float As[2][BK][BM+4];
    __shared__ float Bs[2][BK][BN+4];

    int tid = threadIdx.x;
    int tx = tid & 15, ty = tid >> 4;
    int m0 = blockIdx.y * BM;
    int n0 = blockIdx.x * BN;
    int kBegin = SPLIT ? blockIdx.z * kSlice : 0;
    int kCount = SPLIT ? kSlice : Kd;

    float acc[TM][TN];
#pragma unroll
    for (int i = 0; i < TM; i++)
#pragma unroll
        for (int j = 0; j < TN; j++) acc[i][j] = 0.f;

    auto loadTiles = [&](int k0, int buf) {
        {
            int m = tid >> 1;
            int kv = (tid & 1) * 4;
            float4 v = *reinterpret_cast<const float4*>(A + (size_t)(m0+m)*lda + k0 + kv);
            As[buf][kv+0][m] = v.x; As[buf][kv+1][m] = v.y;
            As[buf][kv+2][m] = v.z; As[buf][kv+3][m] = v.w;
        }
#pragma unroll
        for (int f = tid; f < BN*BK/4; f += 256) {
            int n = f >> 1;
            int kv = (f & 1) * 4;
            float4 v = make_float4(0.f,0.f,0.f,0.f);
            if (n0 + n < N)
                v = *reinterpret_cast<const float4*>(Bw + (size_t)(n0+n)*ldb + k0 + kv);
            Bs[buf][kv+0][n] = v.x; Bs[buf][kv+1][n] = v.y;
            Bs[buf][kv+2][n] = v.z; Bs[buf][kv+3][n] = v.w;
        }
    };

    loadTiles(kBegin, 0);
    __syncthreads();

    int nIter = kCount / BK;
    for (int it = 0; it < nIter; it++) {
        int buf = it & 1;
        if (it + 1 < nIter) loadTiles(kBegin + (it+1)*BK, buf ^ 1);
#pragma unroll
        for (int k = 0; k < BK; k++) {
            float am[TM], bn[TN];
            {
                float4 a0 = *reinterpret_cast<const float4*>(&As[buf][k][ty*TM]);
                float4 a1 = *reinterpret_cast<const float4*>(&As[buf][k][ty*TM+4]);
                am[0]=a0.x; am[1]=a0.y; am[2]=a0.z; am[3]=a0.w;
                am[4]=a1.x; am[5]=a1.y; am[6]=a1.z; am[7]=a1.w;
            }
            if (TN == 8) {
                float4 b0 = *reinterpret_cast<const float4*>(&Bs[buf][k][tx*TN]);
                float4 b1 = *reinterpret_cast<const float4*>(&Bs[buf][k][tx*TN+4]);
                bn[0]=b0.x; bn[1]=b0.y; bn[2]=b0.z; bn[3]=b0.w;
                bn[4]=b1.x; bn[5]=b1.y; bn[6]=b1.z; bn[7]=b1.w;
            } else {
                float4 b0 = *reinterpret_cast<const float4*>(&Bs[buf][k][tx*TN]);
                bn[0]=b0.x; bn[1]=b0.y; bn[2]=b0.z; bn[3]=b0.w;
            }
#pragma unroll
            for (int i = 0; i < TM; i++)
#pragma unroll
                for (int j = 0; j < TN; j++)
                    acc[i][j] = fmaf(am[i], bn[j], acc[i][j]);
        }
        __syncthreads();
    }

    float* outp = SPLIT ? (part + (size_t)blockIdx.z * M * ldc) : C;
#pragma unroll
    for (int i = 0; i < TM; i++) {
        int m = m0 + ty*TM + i;
#pragma unroll
        for (int j = 0; j < TN; j++) {
            int n = n0 + tx*TN + j;
            if (n < N) {
                float v = acc[i][j];
                if (!SPLIT) {
                    if (HAS_BIAS) v += bias[n];
                    if (ACT == 1) v = gelu_exact(v);
                    else if (ACT == 2) v = (v > 20.f) ? v : log1pf(__expf(v));
                    if (HAS_RES) v += res[(size_t)m*ldc + n];
                }
                outp[(size_t)m*ldc + n] = v;
            }
        }
    }
}

// reduce split-K partials
__global__ void reduce_splitk(const float* __restrict__ part, float* __restrict__ out, int MN) {
    int i = blockIdx.x*256 + threadIdx.x;
    if (i >= MN) return;
    float s = 0.f;
#pragma unroll
    for (int k = 0; k < XSPLIT; k++) s += part[(size_t)k*MN + i];
    out[i] = s;
}

// -------------------- causal depthwise conv (K=4) + silu, float4 --------------------
__global__ void conv_silu_kernel(const float* __restrict__ xz,
                                 const float* __restrict__ cw,
                                 const float* __restrict__ cb,
                                 float* __restrict__ xc) {
    int idx = blockIdx.x * blockDim.x + threadIdx.x;   // over RTOT * DII/4
    if (idx >= RTOT*(DII/4)) return;
    int d4 = idx % (DII/4);
    int r  = idx / (DII/4);
    int d  = d4 * 4;
    int s  = r & (SS-1);

    float4 w0 = *reinterpret_cast<const float4*>(cw + (d+0)*KKC);
    float4 w1 = *reinterpret_cast<const float4*>(cw + (d+1)*KKC);
    float4 w2 = *reinterpret_cast<const float4*>(cw + (d+2)*KKC);
    float4 w3 = *reinterpret_cast<const float4*>(cw + (d+3)*KKC);
    const float* wk[4] = {&w0.x, &w1.x, &w2.x, &w3.x};

    float4 acc = *reinterpret_cast<const float4*>(cb + d);
    float* accp = &acc.x;
#pragma unroll
    for (int k = 0; k < KKC; k++) {
        int sk = s - (KKC-1) + k;
        if (sk >= 0) {
            float4 v = *reinterpret_cast<const float4*>(
                xz + (size_t)(r + sk - s)*(2*DII) + d);
            accp[0] = fmaf(v.x, wk[0][k], accp[0]);
            accp[1] = fmaf(v.y, wk[1][k], accp[1]);
            accp[2] = fmaf(v.z, wk[2][k], accp[2]);
            accp[3] = fmaf(v.w, wk[3][k], accp[3]);
        }
    }
#pragma unroll
    for (int j = 0; j < 4; j++) {
        float a = accp[j];
        float sg = 1.f / (1.f + __expf(-a));
        accp[j] = a * sg;
    }
    *reinterpret_cast<float4*>(xc + (size_t)r*DII + d) = acc;
}

// -------------------- selective scan: full smem staging (dl/u/z/BC) --------------------
__global__ __launch_bounds__(128) void scan_kernel(
    const float* __restrict__ delta, const float* __restrict__ dbc,
    const float* __restrict__ xc,    const float* __restrict__ xz,
    const float* __restrict__ A_log, const float* __restrict__ Dw,
    float* __restrict__ y)
{
    const int ST = 16;   // steps per block
    int b  = blockIdx.y;
    int d0 = blockIdx.x*128;
    int d  = d0 + threadIdx.x;

    float Av[DSS];
#pragma unroll
    for (int i = 0; i < DSS; i++) Av[i] = -__expf(A_log[d*DSS + i]);
    float a0 = Av[0];
    bool fast = true;
#pragma unroll
    for (int i = 0; i < DSS; i++)
        if (fabsf(Av[i] - (float)(i+1)*a0) > 1e-4f*fabsf(Av[i]) + 1e-6f) fast = false;

    float Dd = Dw[d];
    float h[DSS];
#pragma unroll
    for (int i = 0; i < DSS; i++) h[i] = 0.f;

    __shared__ float sBC[ST][33];
    __shared__ float sDL[ST][128];
    __shared__ float sU [ST][128];
    __shared__ float sZ [ST][128];

    size_t rBase = (size_t)b*SS;

    for (int s0 = 0; s0 < SS; s0 += ST) {
        __syncthreads();
#pragma unroll
        for (int q = 0; q < ST; q++) {
            int f = threadIdx.x + q*128;
            int j = f >> 7, dd = f & 127;
            size_t row = rBase + s0 + j;
            sDL[j][dd] = delta[row*DII + d0 + dd];
            sU [j][dd] = xc   [row*DII + d0 + dd];
            sZ [j][dd] = xz   [row*2*DII + DII + d0 + dd];
        }
#pragma unroll
        for (int q = 0; q < (ST*32)/128; q++) {
            int f = threadIdx.x + q*128;
            int j = f >> 5, c = f & 31;
            sBC[j][c] = dbc[(rBase + s0 + j)*DBCW + DTRR + c];
        }
        __syncthreads();

        for (int j = 0; j < ST; j++) {
            float dl = sDL[j][threadIdx.x];
            float u  = sU [j][threadIdx.x];
            float z  = sZ [j][threadIdx.x];
            float du = dl*u;
            float yacc = 0.f;
            if (fast) {
                float t = __expf(dl*a0);
                float p = 1.f;
#pragma unroll
                for (int i = 0; i < DSS; i++) {
                    p *= t;
                    h[i] = fmaf(h[i], p, du*sBC[j][i]);
                    yacc = fmaf(h[i], sBC[j][16+i], yacc);
                }
            } else {
#pragma unroll
                for (int i = 0; i < DSS; i++) {
                    float e = __expf(dl*Av[i]);
                    h[i] = fmaf(h[i], e, du*sBC[j][i]);
                    yacc = fmaf(h[i], sBC[j][16+i], yacc);
                }
            }
            float ys = yacc + u*Dd;
            float sg = 1.f / (1.f + __expf(-z));
            y[(rBase + s0 + j)*DII + d] = ys * (z*sg);
        }
    }
}

// -------------------- final LN + head --------------------
__global__ __launch_bounds__(256) void headrow_kernel(const float* __restrict__ x,
                                                      const float* __restrict__ w,
                                                      const float* __restrict__ b,
                                                      const float* __restrict__ wh,
                                                      float* __restrict__ rowdot) {
    int row = blockIdx.x;
    const float* xr = x + (size_t)row*DMM;
    float v[3];
    float s = 0.f, sq = 0.f;
#pragma unroll
    for (int i = 0; i < 3; i++) {
        v[i] = xr[threadIdx.x + 256*i];
        s += v[i]; sq += v[i]*v[i];
    }
    __shared__ float sms[8], smq[8];
    __shared__ float mu_s, rs_s;
#pragma unroll
    for (int o = 16; o > 0; o >>= 1) {
        s  += __shfl_xor_sync(0xffffffffu, s,  o);
        sq += __shfl_xor_sync(0xffffffffu, sq, o);
    }
    int lane = threadIdx.x & 31, wid = threadIdx.x >> 5;
    if (lane == 0) { sms[wid] = s; smq[wid] = sq; }
    __syncthreads();
    if (threadIdx.x == 0) {
        float S = 0.f, Q = 0.f;
        for (int i = 0; i < 8; i++) { S += sms[i]; Q += smq[i]; }
        float mu = S * (1.0f/DMM);
        float var = Q * (1.0f/DMM) - mu*mu;
        mu_s = mu; rs_s = rsqrtf(var + 1e-5f);
    }
    __syncthreads();
    float mu = mu_s, rs = rs_s;
    float p = 0.f;
#pragma unroll
    for (int i = 0; i < 3; i++) {
        int d = threadIdx.x + 256*i;
        p = fmaf((v[i]-mu)*rs*w[d] + b[d], wh[d], p);
    }
#pragma unroll
    for (int o = 16; o > 0; o >>= 1) p += __shfl_xor_sync(0xffffffffu, p, o);
    __syncthreads();
    if (lane == 0) sms[wid] = p;
    __syncthreads();
    if (threadIdx.x == 0) {
        float S = 0.f;
        for (int i = 0; i < 8; i++) S += sms[i];
        rowdot[row] = S;
    }
}

__global__ __launch_bounds__(256) void final_kernel(const float* __restrict__ rowdot,
                                                    const float* __restrict__ b_head,
                                                    float* __restrict__ out) {
    int b = blockIdx.x;
    float s = 0.f;
    for (int j = threadIdx.x; j < SS; j += 256) s += rowdot[b*SS + j];
    __shared__ float sms[8];
#pragma unroll
    for (int o = 16; o > 0; o >>= 1) s += __shfl_xor_sync(0xffffffffu, s, o);
    int lane = threadIdx.x & 31, wid = threadIdx.x >> 5;
    if (lane == 0) sms[wid] = s;
    __syncthreads();
    if (threadIdx.x == 0) {
        float S = 0.f;
        for (int i = 0; i < 8; i++) S += sms[i];
        out[b] = b_head[0] + S * (1.0f/SS);
    }
}

// -------------------- launch --------------------
extern "C" void kernel_launch(void* const* d_in, const int* in_sizes, int n_in,
                              void* d_out, int out_size) {
    const float* x        = (const float*)d_in[0];
    const float* w_in     = (const float*)d_in[1];
    const float* b_in     = (const float*)d_in[2];
    const float* pe       = (const float*)d_in[3];
    const float* ln1_w    = (const float*)d_in[4];
    const float* ln1_b    = (const float*)d_in[5];
    const float* w_inproj = (const float*)d_in[6];
    const float* conv_w   = (const float*)d_in[7];
    const float* conv_b   = (const float*)d_in[8];
    const float* w_xproj  = (const float*)d_in[9];
    const float* w_dt     = (const float*)d_in[10];
    const float* b_dt     = (const float*)d_in[11];
    const float* A_log    = (const float*)d_in[12];
    const float* Dmat     = (const float*)d_in[13];
    const float* w_outproj= (const float*)d_in[14];
    const float* ln2_w    = (const float*)d_in[15];
    const float* ln2_b    = (const float*)d_in[16];
    const float* ff_w1    = (const float*)d_in[17];
    const float* ff_b1    = (const float*)d_in[18];
    const float* ff_w2    = (const float*)d_in[19];
    const float* ff_b2    = (const float*)d_in[20];
    const float* lnf_w    = (const float*)d_in[21];
    const float* lnf_b    = (const float*)d_in[22];
    const float* w_head   = (const float*)d_in[23];
    const float* b_head   = (const float*)d_in[24];
    float* out = (float*)d_out;

    float *h, *xln, *xz, *xc, *dbc, *delta, *y, *part, *rowdot;
    cudaGetSymbolAddress((void**)&h,      g_h);
    cudaGetSymbolAddress((void**)&xln,    g_xln);
    cudaGetSymbolAddress((void**)&xz,     g_xz);
    cudaGetSymbolAddress((void**)&xc,     g_xc);
    cudaGetSymbolAddress((void**)&dbc,    g_dbc);
    cudaGetSymbolAddress((void**)&delta,  g_delta);
    cudaGetSymbolAddress((void**)&y,      g_y);
    cudaGetSymbolAddress((void**)&part,   g_part);
    cudaGetSymbolAddress((void**)&rowdot, g_rowdot);

    // dynamic smem: 4 stages * (BM + BN) * 20 floats
    const int SM128 = 4*(128+128)*20*4;   // 81,920 B
    const int SM64  = 4*(128+64)*20*4;    // 61,440 B
    cudaFuncSetAttribute(gemm_tc<128,0,false,false>, cudaFuncAttributeMaxDynamicSharedMemorySize, SM128);
    cudaFuncSetAttribute(gemm_tc<128,1,true,false>,  cudaFuncAttributeMaxDynamicSharedMemorySize, SM128);
    cudaFuncSetAttribute(gemm_tc<128,2,true,false>,  cudaFuncAttributeMaxDynamicSharedMemorySize, SM128);
    cudaFuncSetAttribute(gemm_tc<64,0,false,true>,   cudaFuncAttributeMaxDynamicSharedMemorySize, SM64);
    cudaFuncSetAttribute(gemm_tc<64,0,true,true>,    cudaFuncAttributeMaxDynamicSharedMemorySize, SM64);

    const int GM = RTOT/128;  // 16 row-blocks

    embed_kernel<<<(RTOT*DMM + 255)/256, 256>>>(x, w_in, b_in, pe, h);

    for (int l = 0; l < LLN; l++) {
        // ln1
        ln_kernel<<<RTOT, 256>>>(h, ln1_w + l*DMM, ln1_b + l*DMM, xln);
        // inproj: xz[2048,3072] = xln @ w_inproj^T   (TC tf32)
        gemm_tc<128,0,false,false><<<dim3((2*DII)/128, GM), 256, SM128>>>(
            xln, DMM, w_inproj + (size_t)l*2*DII*DMM, DMM, nullptr, nullptr,
            xz, 2*DII, RTOT, 2*DII, DMM);
        // conv + silu (float4)
        conv_silu_kernel<<<(RTOT*(DII/4) + 255)/256, 256>>>(
            xz, conv_w + (size_t)l*DII*KKC, conv_b + l*DII, xc);
        // xproj (split-K, fp32): dbc[2048,80] = xc @ w_xproj^T
        gemm2<128,0,false,false,true><<<dim3(1, GM, XSPLIT), 256>>>(
            xc, DII, w_xproj + (size_t)l*DBCW*DII, DII, nullptr, nullptr,
            nullptr, DBCW, RTOT, DBCW, DII, DII/XSPLIT, part);
        reduce_splitk<<<(RTOT*DBCW + 255)/256, 256>>>(part, dbc, RTOT*DBCW);
        // delta = softplus(dbc[:, :48] @ w_dt^T + b_dt)   (TC tf32, K=48)
        gemm_tc<128,2,true,false><<<dim3(DII/128, GM), 256, SM128>>>(
            dbc, DBCW, w_dt + (size_t)l*DII*DTRR, DTRR, b_dt + l*DII, nullptr,
            delta, DII, RTOT, DII, DTRR);
        // scan -> y (smem-staged operands)
        scan_kernel<<<dim3(DII/128, BB), 128>>>(
            delta, dbc, xc, xz, A_log + (size_t)l*DII*DSS, Dmat + l*DII, y);
        // h += y @ w_outproj^T   (TC tf32)
        gemm_tc<64,0,false,true><<<dim3(DMM/64, GM), 256, SM64>>>(
            y, DII, w_outproj + (size_t)l*DMM*DII, DII, nullptr, h,
            h, DMM, RTOT, DMM, DII);
        // ln2
        ln_kernel<<<RTOT, 256>>>(h, ln2_w + l*DMM, ln2_b + l*DMM, xln);
        // ff1: f = gelu(xln @ ff_w1^T + b1)   (TC tf32)
        gemm_tc<128,1,true,false><<<dim3((2*DMM)/128, GM), 256, SM128>>>(
            xln, DMM, ff_w1 + (size_t)l*2*DMM*DMM, DMM, ff_b1 + l*2*DMM, nullptr,
            y, 2*DMM, RTOT, 2*DMM, DMM);
        // h += f @ ff_w2^T + b2   (TC tf32)
        gemm_tc<64,0,true,true><<<dim3(DMM/64, GM), 256, SM64>>>(
            y, 2*DMM, ff_w2 + (size_t)l*DMM*2*DMM, 2*DMM, ff_b2 + l*DMM, h,
            h, DMM, RTOT, DMM, 2*DMM);
    }

    headrow_kernel<<<RTOT, 256>>>(h, lnf_w, lnf_b, w_head, rowdot);
    final_kernel<<<BB, 256>>>(rowdot, b_head, out);
}

// round 10
// speedup vs baseline: 1.4740x; 1.4740x over previous
#include <cuda_runtime.h>
#include <math.h>
#include <stdint.h>

#define BB   4
#define SS   512
#define DMM  768
#define LLN  2
#define DII  1536
#define DSS  16
#define KKC  4
#define DTRR 48
#define RTOT (BB*SS)         // 2048
#define DBCW (DTRR + 2*DSS)  // 80
#define XSPLIT 16            // split-K slices for xproj

// -------------------- scratch (device globals; no allocs) --------------------
__device__ __align__(256) float g_h    [RTOT*DMM];
__device__ __align__(256) float g_xln  [RTOT*DMM];
__device__ __align__(256) float g_xz   [RTOT*2*DII];
__device__ __align__(256) float g_xc   [RTOT*DII];
__device__ __align__(256) float g_dbc  [RTOT*DBCW];
__device__ __align__(256) float g_delta[RTOT*DII];
__device__ __align__(256) float g_y    [RTOT*DII];
__device__ __align__(256) float g_part [XSPLIT*RTOT*DBCW];
__device__ __align__(256) float g_rowdot[RTOT];

// -------------------- helpers --------------------
__device__ __forceinline__ void mma_tf32(float* c, const uint32_t* a, const uint32_t* b) {
    asm volatile(
        "mma.sync.aligned.m16n8k8.row.col.f32.tf32.tf32.f32 "
        "{%0,%1,%2,%3}, {%4,%5,%6,%7}, {%8,%9}, {%0,%1,%2,%3};"
        : "+f"(c[0]), "+f"(c[1]), "+f"(c[2]), "+f"(c[3])
        : "r"(a[0]), "r"(a[1]), "r"(a[2]), "r"(a[3]), "r"(b[0]), "r"(b[1]));
}
__device__ __forceinline__ void cp_async16(uint32_t smem_addr, const float* gptr) {
    asm volatile("cp.async.cg.shared.global [%0], [%1], 16;\n"
                 :: "r"(smem_addr), "l"(gptr));
}
__device__ __forceinline__ void cp_commit() {
    asm volatile("cp.async.commit_group;\n" ::: "memory");
}
template<int N>
__device__ __forceinline__ void cp_wait() {
    asm volatile("cp.async.wait_group %0;\n" :: "n"(N) : "memory");
}
__device__ __forceinline__ float gelu_exact(float v) {
    return 0.5f * v * (1.0f + erff(v * 0.70710678118654752f));
}

// -------------------- embed --------------------
__global__ void embed_kernel(const float* __restrict__ x, const float* __restrict__ w_in,
                             const float* __restrict__ b_in, const float* __restrict__ pe,
                             float* __restrict__ h) {
    int idx = blockIdx.x * blockDim.x + threadIdx.x;
    if (idx >= RTOT*DMM) return;
    int r = idx / DMM;
    int d = idx - r*DMM;
    int s = r & (SS-1);
    h[idx] = x[r]*w_in[d] + b_in[d] + pe[s*DMM + d];
}

// -------------------- layernorm --------------------
__global__ __launch_bounds__(256) void ln_kernel(const float* __restrict__ x,
                                                 const float* __restrict__ w,
                                                 const float* __restrict__ b,
                                                 float* __restrict__ y) {
    int row = blockIdx.x;
    const float* xr = x + (size_t)row*DMM;
    float v[3];
    float s = 0.f, sq = 0.f;
#pragma unroll
    for (int i = 0; i < 3; i++) {
        v[i] = xr[threadIdx.x + 256*i];
        s  += v[i];
        sq += v[i]*v[i];
    }
    __shared__ float sms[8], smq[8];
    __shared__ float mu_s, rs_s;
#pragma unroll
    for (int o = 16; o > 0; o >>= 1) {
        s  += __shfl_xor_sync(0xffffffffu, s,  o);
        sq += __shfl_xor_sync(0xffffffffu, sq, o);
    }
    int lane = threadIdx.x & 31, wid = threadIdx.x >> 5;
    if (lane == 0) { sms[wid] = s; smq[wid] = sq; }
    __syncthreads();
    if (threadIdx.x == 0) {
        float S = 0.f, Q = 0.f;
        for (int i = 0; i < 8; i++) { S += sms[i]; Q += smq[i]; }
        float mu = S * (1.0f/DMM);
        float var = Q * (1.0f/DMM) - mu*mu;
        mu_s = mu;
        rs_s = rsqrtf(var + 1e-5f);
    }
    __syncthreads();
    float mu = mu_s, rs = rs_s;
    float* yr = y + (size_t)row*DMM;
#pragma unroll
    for (int i = 0; i < 3; i++) {
        int d = threadIdx.x + 256*i;
        yr[d] = (v[i]-mu)*rs*w[d] + b[d];
    }
}

// -------------------- tensor-core tf32 GEMM, cp.async 4-stage, no-cvt (proven) ------
template<int BN, int ACT, bool HAS_BIAS, bool HAS_RES>
__global__ __launch_bounds__(256, 2) void gemm_tc(
    const float* __restrict__ A, int lda,
    const float* __restrict__ Bw, int ldb,     // (N, K) row-major
    const float* __restrict__ bias,
    const float* res,
    float* C, int ldc,
    int M, int N, int Kd)
{
    const int BM = 128, SK = 20, STG = 4;
    const int WC = (BN == 128) ? 4 : 2;
    const int WARP_M = (BN == 128) ? 64 : 32;
    const int MT = WARP_M / 16;
    const int NT = 4;

    extern __shared__ float sm[];
    float* As = sm;
    float* Bs = sm + STG*BM*SK;

    int tid  = threadIdx.x;
    int wid  = tid >> 5;
    int lane = tid & 31;
    int g    = lane >> 2;
    int tg   = lane & 3;
    int wm = (wid / WC) * WARP_M;
    int wn = (wid % WC) * 32;
    int m0 = blockIdx.y * BM;
    int n0 = blockIdx.x * BN;

    float acc[MT][NT][4];
#pragma unroll
    for (int i = 0; i < MT; i++)
#pragma unroll
        for (int j = 0; j < NT; j++)
#pragma unroll
            for (int q = 0; q < 4; q++) acc[i][j][q] = 0.f;

    auto stageLoad = [&](int k0, int buf) {
        float* Asb = As + buf*BM*SK;
        float* Bsb = Bs + buf*BN*SK;
#pragma unroll
        for (int q = 0; q < 2; q++) {
            int f = tid + q*256;
            int m = f >> 2, kv = (f & 3) * 4;
            cp_async16((uint32_t)__cvta_generic_to_shared(Asb + m*SK + kv),
                       A + (size_t)(m0+m)*lda + k0 + kv);
        }
#pragma unroll
        for (int q = 0; q < BN/64; q++) {
            int f = tid + q*256;
            int n = f >> 2, kv = (f & 3) * 4;
            cp_async16((uint32_t)__cvta_generic_to_shared(Bsb + n*SK + kv),
                       Bw + (size_t)(n0+n)*ldb + k0 + kv);
        }
    };

    int nIter = Kd / 16;
    stageLoad(0, 0);  cp_commit();
    stageLoad(16, 1); cp_commit();
    stageLoad(32, 2); cp_commit();

    for (int it = 0; it < nIter; it++) {
        cp_wait<2>();
        __syncthreads();

        int buf = it & 3;
        const float* Asb = As + buf*BM*SK;
        const float* Bsb = Bs + buf*BN*SK;
#pragma unroll
        for (int kk = 0; kk < 2; kk++) {
            int kb = kk*8;
            uint32_t bf[NT][2];
#pragma unroll
            for (int tn = 0; tn < NT; tn++) {
                int n = wn + tn*8 + g;
                bf[tn][0] = __float_as_uint(Bsb[n*SK + kb + tg]);
                bf[tn][1] = __float_as_uint(Bsb[n*SK + kb + tg + 4]);
            }
#pragma unroll
            for (int tm = 0; tm < MT; tm++) {
                int r = wm + tm*16 + g;
                uint32_t af[4];
                af[0] = __float_as_uint(Asb[(r    )*SK + kb + tg    ]);
                af[1] = __float_as_uint(Asb[(r + 8)*SK + kb + tg    ]);
                af[2] = __float_as_uint(Asb[(r    )*SK + kb + tg + 4]);
                af[3] = __float_as_uint(Asb[(r + 8)*SK + kb + tg + 4]);
#pragma unroll
                for (int tn = 0; tn < NT; tn++)
                    mma_tf32(acc[tm][tn], af, bf[tn]);
            }
        }

        int nxt = it + 3;
        if (nxt < nIter) stageLoad(nxt*16, nxt & 3);
        cp_commit();
    }

    // epilogue
#pragma unroll
    for (int tm = 0; tm < MT; tm++) {
        int mrow = m0 + wm + tm*16 + g;
#pragma unroll
        for (int tn = 0; tn < NT; tn++) {
            int ncol = n0 + wn + tn*8 + 2*tg;
            float b0v = 0.f, b1v = 0.f;
            if (HAS_BIAS) { b0v = bias[ncol]; b1v = bias[ncol+1]; }
            float v0 = acc[tm][tn][0] + b0v;
            float v1 = acc[tm][tn][1] + b1v;
            float v2 = acc[tm][tn][2] + b0v;
            float v3 = acc[tm][tn][3] + b1v;
            if (ACT == 1) {
                v0 = gelu_exact(v0); v1 = gelu_exact(v1);
                v2 = gelu_exact(v2); v3 = gelu_exact(v3);
            } else if (ACT == 2) {
                v0 = (v0 > 20.f) ? v0 : log1pf(__expf(v0));
                v1 = (v1 > 20.f) ? v1 : log1pf(__expf(v1));
                v2 = (v2 > 20.f) ? v2 : log1pf(__expf(v2));
                v3 = (v3 > 20.f) ? v3 : log1pf(__expf(v3));
            }
            size_t o0 = (size_t)mrow*ldc + ncol;
            size_t o1 = (size_t)(mrow+8)*ldc + ncol;
            if (HAS_RES) {
                float2 r0 = *reinterpret_cast<const float2*>(res + o0);
                float2 r1 = *reinterpret_cast<const float2*>(res + o1);
                v0 += r0.x; v1 += r0.y; v2 += r1.x; v3 += r1.y;
            }
            *reinterpret_cast<float2*>(C + o0) = make_float2(v0, v1);
            *reinterpret_cast<float2*>(C + o1) = make_float2(v2, v3);
        }
    }
}

// -------------------- fp32 SIMT GEMM (xproj split-K) --------------------
// NOTE: TN==8 B-fragment branch is REQUIRED for BN=128.
template<int BN, int ACT, bool HAS_BIAS, bool HAS_RES, bool SPLIT>
__global__ __launch_bounds__(256) void gemm2(
    const float* __restrict__ A, int lda,
    const float* __restrict__ Bw, int ldb,
    const float* __restrict__ bias,
    const float* res,
    float* C, int ldc,
    int M, int N, int Kd, int kSlice,
    float* part)
{
    const int BM = 128, BK = 8, TM = 8;
    const int TN = BN / 16;
    __shared__ float As[2][BK][BM+4];
    __shared__ float Bs[2][BK][BN+4];

    int tid = threadIdx.x;
    int tx = tid & 15, ty = tid >> 4;
    int m0 = blockIdx.y * BM;
    int n0 = blockIdx.x * BN;
    int kBegin = SPLIT ? blockIdx.z * kSlice : 0;
    int kCount = SPLIT ? kSlice : Kd;

    float acc[TM][TN];
#pragma unroll
    for (int i = 0; i < TM; i++)
#pragma unroll
        for (int j = 0; j < TN; j++) acc[i][j] = 0.f;

    auto loadTiles = [&](int k0, int buf) {
        {
            int m = tid >> 1;
            int kv = (tid & 1) * 4;
            float4 v = *reinterpret_cast<const float4*>(A + (size_t)(m0+m)*lda + k0 + kv);
            As[buf][kv+0][m] = v.x; As[buf][kv+1][m] = v.y;
            As[buf][kv+2][m] = v.z; As[buf][kv+3][m] = v.w;
        }
#pragma unroll
        for (int f = tid; f < BN*BK/4; f += 256) {
            int n = f >> 1;
            int kv = (f & 1) * 4;
            float4 v = make_float4(0.f,0.f,0.f,0.f);
            if (n0 + n < N)
                v = *reinterpret_cast<const float4*>(Bw + (size_t)(n0+n)*ldb + k0 + kv);
            Bs[buf][kv+0][n] = v.x; Bs[buf][kv+1][n] = v.y;
            Bs[buf][kv+2][n] = v.z; Bs[buf][kv+3][n] = v.w;
        }
    };

    loadTiles(kBegin, 0);
    __syncthreads();

    int nIter = kCount / BK;
    for (int it = 0; it < nIter; it++) {
        int buf = it & 1;
        if (it + 1 < nIter) loadTiles(kBegin + (it+1)*BK, buf ^ 1);
#pragma unroll
        for (int k = 0; k < BK; k++) {
            float am[TM], bn[TN];
            {
                float4 a0 = *reinterpret_cast<const float4*>(&As[buf][k][ty*TM]);
                float4 a1 = *reinterpret_cast<const float4*>(&As[buf][k][ty*TM+4]);
                am[0]=a0.x; am[1]=a0.y; am[2]=a0.z; am[3]=a0.w;
                am[4]=a1.x; am[5]=a1.y; am[6]=a1.z; am[7]=a1.w;
            }
            if (TN == 8) {
                float4 b0 = *reinterpret_cast<const float4*>(&Bs[buf][k][tx*TN]);
                float4 b1 = *reinterpret_cast<const float4*>(&Bs[buf][k][tx*TN+4]);
                bn[0]=b0.x; bn[1]=b0.y; bn[2]=b0.z; bn[3]=b0.w;
                bn[4]=b1.x; bn[5]=b1.y; bn[6]=b1.z; bn[7]=b1.w;
            } else {
                float4 b0 = *reinterpret_cast<const float4*>(&Bs[buf][k][tx*TN]);
                bn[0]=b0.x; bn[1]=b0.y; bn[2]=b0.z; bn[3]=b0.w;
            }
#pragma unroll
            for (int i = 0; i < TM; i++)
#pragma unroll
                for (int j = 0; j < TN; j++)
                    acc[i][j] = fmaf(am[i], bn[j], acc[i][j]);
        }
        __syncthreads();
    }

    float* outp = SPLIT ? (part + (size_t)blockIdx.z * M * ldc) : C;
#pragma unroll
    for (int i = 0; i < TM; i++) {
        int m = m0 + ty*TM + i;
#pragma unroll
        for (int j = 0; j < TN; j++) {
            int n = n0 + tx*TN + j;
            if (n < N) {
                float v = acc[i][j];
                if (!SPLIT) {
                    if (HAS_BIAS) v += bias[n];
                    if (ACT == 1) v = gelu_exact(v);
                    else if (ACT == 2) v = (v > 20.f) ? v : log1pf(__expf(v));
                    if (HAS_RES) v += res[(size_t)m*ldc + n];
                }
                outp[(size_t)m*ldc + n] = v;
            }
        }
    }
}

// reduce split-K partials
__global__ void reduce_splitk(const float* __restrict__ part, float* __restrict__ out, int MN) {
    int i = blockIdx.x*256 + threadIdx.x;
    if (i >= MN) return;
    float s = 0.f;
#pragma unroll
    for (int k = 0; k < XSPLIT; k++) s += part[(size_t)k*MN + i];
    out[i] = s;
}

// -------------------- causal depthwise conv (K=4) + silu (R5 scalar, proven) --------
__global__ void conv_silu_kernel(const float* __restrict__ xz,
                                 const float* __restrict__ cw,
                                 const float* __restrict__ cb,
                                 float* __restrict__ xc) {
    int idx = blockIdx.x * blockDim.x + threadIdx.x;
    if (idx >= RTOT*DII) return;
    int d = idx % DII;
    int r = idx / DII;
    int s = r & (SS-1);
    float acc = cb[d];
#pragma unroll
    for (int k = 0; k < KKC; k++) {
        int sk = s - (KKC-1) + k;
        if (sk >= 0)
            acc = fmaf(xz[(size_t)(r + sk - s)*(2*DII) + d], cw[d*KKC + k], acc);
    }
    float sg = 1.f / (1.f + __expf(-acc));
    xc[idx] = acc * sg;
}

// -------------------- selective scan: double-buffered cp.async staging --------------
// ST=8 steps/block, two buffers; next block's loads overlap current block's compute.
// Arithmetic order identical to R5 (rel_err preserved).
__global__ __launch_bounds__(128) void scan_kernel(
    const float* __restrict__ delta, const float* __restrict__ dbc,
    const float* __restrict__ xc,    const float* __restrict__ xz,
    const float* __restrict__ A_log, const float* __restrict__ Dw,
    float* __restrict__ y)
{
    const int ST = 8;
    int b  = blockIdx.y;
    int d0 = blockIdx.x*128;
    int d  = d0 + threadIdx.x;
    int tid = threadIdx.x;

    float Av[DSS];
#pragma unroll
    for (int i = 0; i < DSS; i++) Av[i] = -__expf(A_log[d*DSS + i]);
    float a0 = Av[0];
    bool fast = true;
#pragma unroll
    for (int i = 0; i < DSS; i++)
        if (fabsf(Av[i] - (float)(i+1)*a0) > 1e-4f*fabsf(Av[i]) + 1e-6f) fast = false;

    float Dd = Dw[d];
    float h[DSS];
#pragma unroll
    for (int i = 0; i < DSS; i++) h[i] = 0.f;

    // double-buffered staging; sBC stride 32 (16B-aligned rows for cp.async;
    // reads are warp-broadcast so no conflicts)
    __shared__ float sDL[2][ST][128];
    __shared__ float sU [2][ST][128];
    __shared__ float sZ [2][ST][128];
    __shared__ float sBC[2][ST][32];

    size_t rBase = (size_t)b*SS;

    auto stage = [&](int blk, int buf) {
        int s0 = blk*ST;
        // dl/u/z: ST*128 floats = 256 float4 each -> 2 per thread
#pragma unroll
        for (int q = 0; q < 2; q++) {
            int f = tid + q*128;           // 0..255
            int j = f >> 5, c4 = (f & 31)*4;
            size_t row = rBase + s0 + j;
            cp_async16((uint32_t)__cvta_generic_to_shared(&sDL[buf][j][c4]),
                       delta + row*DII + d0 + c4);
            cp_async16((uint32_t)__cvta_generic_to_shared(&sU[buf][j][c4]),
                       xc + row*DII + d0 + c4);
            cp_async16((uint32_t)__cvta_generic_to_shared(&sZ[buf][j][c4]),
                       xz + row*2*DII + DII + d0 + c4);
        }
        // BC: ST rows x 32 floats = 64 float4 -> threads 0..63
        if (tid < ST*8) {
            int j = tid >> 3, c4 = (tid & 7)*4;
            cp_async16((uint32_t)__cvta_generic_to_shared(&sBC[buf][j][c4]),
                       dbc + (rBase + j + s0)*DBCW + DTRR + c4);
        }
    };

    const int nBlk = SS/ST;   // 64
    stage(0, 0);
    cp_commit();

    for (int blk = 0; blk < nBlk; blk++) {
        int buf = blk & 1;
        cp_wait<0>();          // current buffer ready
        __syncthreads();       // all threads done with previous compute (buf^1)
        if (blk + 1 < nBlk) stage(blk + 1, buf ^ 1);
        cp_commit();

        int s0 = blk*ST;
#pragma unroll
        for (int j = 0; j < ST; j++) {
            float dl = sDL[buf][j][tid];
            float u  = sU [buf][j][tid];
            float z  = sZ [buf][j][tid];
            float du = dl*u;
            float yacc = 0.f;
            if (fast) {
                float t = __expf(dl*a0);
                float p = 1.f;
#pragma unroll
                for (int i = 0; i < DSS; i++) {
                    p *= t;
                    h[i] = fmaf(h[i], p, du*sBC[buf][j][i]);
                    yacc = fmaf(h[i], sBC[buf][j][16+i], yacc);
                }
            } else {
#pragma unroll
                for (int i = 0; i < DSS; i++) {
                    float e = __expf(dl*Av[i]);
                    h[i] = fmaf(h[i], e, du*sBC[buf][j][i]);
                    yacc = fmaf(h[i], sBC[buf][j][16+i], yacc);
                }
            }
            float ys = yacc + u*Dd;
            float sg = 1.f / (1.f + __expf(-z));
            y[(rBase + s0 + j)*DII + d] = ys * (z*sg);
        }
    }
}

// -------------------- final LN + head --------------------
__global__ __launch_bounds__(256) void headrow_kernel(const float* __restrict__ x,
                                                      const float* __restrict__ w,
                                                      const float* __restrict__ b,
                                                      const float* __restrict__ wh,
                                                      float* __restrict__ rowdot) {
    int row = blockIdx.x;
    const float* xr = x + (size_t)row*DMM;
    float v[3];
    float s = 0.f, sq = 0.f;
#pragma unroll
    for (int i = 0; i < 3; i++) {
        v[i] = xr[threadIdx.x + 256*i];
        s += v[i]; sq += v[i]*v[i];
    }
    __shared__ float sms[8], smq[8];
    __shared__ float mu_s, rs_s;
#pragma unroll
    for (int o = 16; o > 0; o >>= 1) {
        s  += __shfl_xor_sync(0xffffffffu, s,  o);
        sq += __shfl_xor_sync(0xffffffffu, sq, o);
    }
    int lane = threadIdx.x & 31, wid = threadIdx.x >> 5;
    if (lane == 0) { sms[wid] = s; smq[wid] = sq; }
    __syncthreads();
    if (threadIdx.x == 0) {
        float S = 0.f, Q = 0.f;
        for (int i = 0; i < 8; i++) { S += sms[i]; Q += smq[i]; }
        float mu = S * (1.0f/DMM);
        float var = Q * (1.0f/DMM) - mu*mu;
        mu_s = mu; rs_s = rsqrtf(var + 1e-5f);
    }
    __syncthreads();
    float mu = mu_s, rs = rs_s;
    float p = 0.f;
#pragma unroll
    for (int i = 0; i < 3; i++) {
        int d = threadIdx.x + 256*i;
        p = fmaf((v[i]-mu)*rs*w[d] + b[d], wh[d], p);
    }
#pragma unroll
    for (int o = 16; o > 0; o >>= 1) p += __shfl_xor_sync(0xffffffffu, p, o);
    __syncthreads();
    if (lane == 0) sms[wid] = p;
    __syncthreads();
    if (threadIdx.x == 0) {
        float S = 0.f;
        for (int i = 0; i < 8; i++) S += sms[i];
        rowdot[row] = S;
    }
}

__global__ __launch_bounds__(256) void final_kernel(const float* __restrict__ rowdot,
                                                    const float* __restrict__ b_head,
                                                    float* __restrict__ out) {
    int b = blockIdx.x;
    float s = 0.f;
    for (int j = threadIdx.x; j < SS; j += 256) s += rowdot[b*SS + j];
    __shared__ float sms[8];
#pragma unroll
    for (int o = 16; o > 0; o >>= 1) s += __shfl_xor_sync(0xffffffffu, s, o);
    int lane = threadIdx.x & 31, wid = threadIdx.x >> 5;
    if (lane == 0) sms[wid] = s;
    __syncthreads();
    if (threadIdx.x == 0) {
        float S = 0.f;
        for (int i = 0; i < 8; i++) S += sms[i];
        out[b] = b_head[0] + S * (1.0f/SS);
    }
}

// -------------------- launch --------------------
extern "C" void kernel_launch(void* const* d_in, const int* in_sizes, int n_in,
                              void* d_out, int out_size) {
    const float* x        = (const float*)d_in[0];
    const float* w_in     = (const float*)d_in[1];
    const float* b_in     = (const float*)d_in[2];
    const float* pe       = (const float*)d_in[3];
    const float* ln1_w    = (const float*)d_in[4];
    const float* ln1_b    = (const float*)d_in[5];
    const float* w_inproj = (const float*)d_in[6];
    const float* conv_w   = (const float*)d_in[7];
    const float* conv_b   = (const float*)d_in[8];
    const float* w_xproj  = (const float*)d_in[9];
    const float* w_dt     = (const float*)d_in[10];
    const float* b_dt     = (const float*)d_in[11];
    const float* A_log    = (const float*)d_in[12];
    const float* Dmat     = (const float*)d_in[13];
    const float* w_outproj= (const float*)d_in[14];
    const float* ln2_w    = (const float*)d_in[15];
    const float* ln2_b    = (const float*)d_in[16];
    const float* ff_w1    = (const float*)d_in[17];
    const float* ff_b1    = (const float*)d_in[18];
    const float* ff_w2    = (const float*)d_in[19];
    const float* ff_b2    = (const float*)d_in[20];
    const float* lnf_w    = (const float*)d_in[21];
    const float* lnf_b    = (const float*)d_in[22];
    const float* w_head   = (const float*)d_in[23];
    const float* b_head   = (const float*)d_in[24];
    float* out = (float*)d_out;

    float *h, *xln, *xz, *xc, *dbc, *delta, *y, *part, *rowdot;
    cudaGetSymbolAddress((void**)&h,      g_h);
    cudaGetSymbolAddress((void**)&xln,    g_xln);
    cudaGetSymbolAddress((void**)&xz,     g_xz);
    cudaGetSymbolAddress((void**)&xc,     g_xc);
    cudaGetSymbolAddress((void**)&dbc,    g_dbc);
    cudaGetSymbolAddress((void**)&delta,  g_delta);
    cudaGetSymbolAddress((void**)&y,      g_y);
    cudaGetSymbolAddress((void**)&part,   g_part);
    cudaGetSymbolAddress((void**)&rowdot, g_rowdot);

    // dynamic smem: 4 stages * (BM + BN) * 20 floats
    const int SM128 = 4*(128+128)*20*4;   // 81,920 B
    const int SM64  = 4*(128+64)*20*4;    // 61,440 B
    cudaFuncSetAttribute(gemm_tc<128,0,false,false>, cudaFuncAttributeMaxDynamicSharedMemorySize, SM128);
    cudaFuncSetAttribute(gemm_tc<128,1,true,false>,  cudaFuncAttributeMaxDynamicSharedMemorySize, SM128);
    cudaFuncSetAttribute(gemm_tc<128,2,true,false>,  cudaFuncAttributeMaxDynamicSharedMemorySize, SM128);
    cudaFuncSetAttribute(gemm_tc<64,0,false,true>,   cudaFuncAttributeMaxDynamicSharedMemorySize, SM64);
    cudaFuncSetAttribute(gemm_tc<64,0,true,true>,    cudaFuncAttributeMaxDynamicSharedMemorySize, SM64);

    const int GM = RTOT/128;  // 16 row-blocks

    embed_kernel<<<(RTOT*DMM + 255)/256, 256>>>(x, w_in, b_in, pe, h);

    for (int l = 0; l < LLN; l++) {
        // ln1
        ln_kernel<<<RTOT, 256>>>(h, ln1_w + l*DMM, ln1_b + l*DMM, xln);
        // inproj: xz[2048,3072] = xln @ w_inproj^T   (TC tf32)
        gemm_tc<128,0,false,false><<<dim3((2*DII)/128, GM), 256, SM128>>>(
            xln, DMM, w_inproj + (size_t)l*2*DII*DMM, DMM, nullptr, nullptr,
            xz, 2*DII, RTOT, 2*DII, DMM);
        // conv + silu (scalar, proven)
        conv_silu_kernel<<<(RTOT*DII + 255)/256, 256>>>(
            xz, conv_w + (size_t)l*DII*KKC, conv_b + l*DII, xc);
        // xproj (split-K, fp32): dbc[2048,80] = xc @ w_xproj^T
        gemm2<128,0,false,false,true><<<dim3(1, GM, XSPLIT), 256>>>(
            xc, DII, w_xproj + (size_t)l*DBCW*DII, DII, nullptr, nullptr,
            nullptr, DBCW, RTOT, DBCW, DII, DII/XSPLIT, part);
        reduce_splitk<<<(RTOT*DBCW + 255)/256, 256>>>(part, dbc, RTOT*DBCW);
        // delta = softplus(dbc[:, :48] @ w_dt^T + b_dt)   (TC tf32, K=48)
        gemm_tc<128,2,true,false><<<dim3(DII/128, GM), 256, SM128>>>(
            dbc, DBCW, w_dt + (size_t)l*DII*DTRR, DTRR, b_dt + l*DII, nullptr,
            delta, DII, RTOT, DII, DTRR);
        // scan -> y (double-buffered cp.async staging)
        scan_kernel<<<dim3(DII/128, BB), 128>>>(
            delta, dbc, xc, xz, A_log + (size_t)l*DII*DSS, Dmat + l*DII, y);
        // h += y @ w_outproj^T   (TC tf32)
        gemm_tc<64,0,false,true><<<dim3(DMM/64, GM), 256, SM64>>>(
            y, DII, w_outproj + (size_t)l*DMM*DII, DII, nullptr, h,
            h, DMM, RTOT, DMM, DII);
        // ln2
        ln_kernel<<<RTOT, 256>>>(h, ln2_w + l*DMM, ln2_b + l*DMM, xln);
        // ff1: f = gelu(xln @ ff_w1^T + b1)   (TC tf32)
        gemm_tc<128,1,true,false><<<dim3((2*DMM)/128, GM), 256, SM128>>>(
            xln, DMM, ff_w1 + (size_t)l*2*DMM*DMM, DMM, ff_b1 + l*2*DMM, nullptr,
            y, 2*DMM, RTOT, 2*DMM, DMM);
        // h += f @ ff_w2^T + b2   (TC tf32)
        gemm_tc<64,0,true,true><<<dim3(DMM/64, GM), 256, SM64>>>(
            y, 2*DMM, ff_w2 + (size_t)l*DMM*2*DMM, 2*DMM, ff_b2 + l*DMM, h,
            h, DMM, RTOT, DMM, 2*DMM);
    }

    headrow_kernel<<<RTOT, 256>>>(h, lnf_w, lnf_b, w_head, rowdot);
    final_kernel<<<BB, 256>>>(rowdot, b_head, out);
}

// round 11
// speedup vs baseline: 1.5067x; 1.0222x over previous
#include <cuda_runtime.h>
#include <math.h>
#include <stdint.h>

#define BB   4
#define SS   512
#define DMM  768
#define LLN  2
#define DII  1536
#define DSS  16
#define KKC  4
#define DTRR 48
#define RTOT (BB*SS)         // 2048
#define DBCW 80              // logical width (48 dt + 16 B + 16 C)
#define DBCP 128             // padded width for TC xproj
#define XSPLIT 16            // split-K slices for xproj

// -------------------- scratch (device globals; no allocs) --------------------
__device__ __align__(256) float g_h    [RTOT*DMM];
__device__ __align__(256) float g_xln  [RTOT*DMM];
__device__ __align__(256) float g_xz   [RTOT*2*DII];
__device__ __align__(256) float g_xc   [RTOT*DII];
__device__ __align__(256) float g_dbc  [RTOT*DBCP];
__device__ __align__(256) float g_delta[RTOT*DII];
__device__ __align__(256) float g_y    [RTOT*DII];
__device__ __align__(256) float g_part [XSPLIT*RTOT*DBCP];
__device__ __align__(256) float g_wxp  [LLN*DBCP*DII];   // padded xproj weights
__device__ __align__(256) float g_rowdot[RTOT];

// -------------------- helpers --------------------
__device__ __forceinline__ void mma_tf32(float* c, const uint32_t* a, const uint32_t* b) {
    asm volatile(
        "mma.sync.aligned.m16n8k8.row.col.f32.tf32.tf32.f32 "
        "{%0,%1,%2,%3}, {%4,%5,%6,%7}, {%8,%9}, {%0,%1,%2,%3};"
        : "+f"(c[0]), "+f"(c[1]), "+f"(c[2]), "+f"(c[3])
        : "r"(a[0]), "r"(a[1]), "r"(a[2]), "r"(a[3]), "r"(b[0]), "r"(b[1]));
}
__device__ __forceinline__ void cp_async16(uint32_t smem_addr, const float* gptr) {
    asm volatile("cp.async.cg.shared.global [%0], [%1], 16;\n"
                 :: "r"(smem_addr), "l"(gptr));
}
__device__ __forceinline__ void cp_commit() {
    asm volatile("cp.async.commit_group;\n" ::: "memory");
}
template<int N>
__device__ __forceinline__ void cp_wait() {
    asm volatile("cp.async.wait_group %0;\n" :: "n"(N) : "memory");
}
__device__ __forceinline__ float gelu_exact(float v) {
    return 0.5f * v * (1.0f + erff(v * 0.70710678118654752f));
}

// -------------------- pad xproj weights: (L,80,1536) -> (L,128,1536), zero rows 80.. --
__global__ void pad_xproj_kernel(const float* __restrict__ w, float* __restrict__ wp) {
    int i = blockIdx.x*256 + threadIdx.x;
    if (i >= LLN*DBCP*DII) return;
    int l   = i / (DBCP*DII);
    int rem = i - l*(DBCP*DII);
    int row = rem / DII;
    int col = rem - row*DII;
    wp[i] = (row < DBCW) ? w[(size_t)l*DBCW*DII + (size_t)row*DII + col] : 0.f;
}

// -------------------- embed --------------------
__global__ void embed_kernel(const float* __restrict__ x, const float* __restrict__ w_in,
                             const float* __restrict__ b_in, const float* __restrict__ pe,
                             float* __restrict__ h) {
    int idx = blockIdx.x * blockDim.x + threadIdx.x;
    if (idx >= RTOT*DMM) return;
    int r = idx / DMM;
    int d = idx - r*DMM;
    int s = r & (SS-1);
    h[idx] = x[r]*w_in[d] + b_in[d] + pe[s*DMM + d];
}

// -------------------- layernorm --------------------
__global__ __launch_bounds__(256) void ln_kernel(const float* __restrict__ x,
                                                 const float* __restrict__ w,
                                                 const float* __restrict__ b,
                                                 float* __restrict__ y) {
    int row = blockIdx.x;
    const float* xr = x + (size_t)row*DMM;
    float v[3];
    float s = 0.f, sq = 0.f;
#pragma unroll
    for (int i = 0; i < 3; i++) {
        v[i] = xr[threadIdx.x + 256*i];
        s  += v[i];
        sq += v[i]*v[i];
    }
    __shared__ float sms[8], smq[8];
    __shared__ float mu_s, rs_s;
#pragma unroll
    for (int o = 16; o > 0; o >>= 1) {
        s  += __shfl_xor_sync(0xffffffffu, s,  o);
        sq += __shfl_xor_sync(0xffffffffu, sq, o);
    }
    int lane = threadIdx.x & 31, wid = threadIdx.x >> 5;
    if (lane == 0) { sms[wid] = s; smq[wid] = sq; }
    __syncthreads();
    if (threadIdx.x == 0) {
        float S = 0.f, Q = 0.f;
        for (int i = 0; i < 8; i++) { S += sms[i]; Q += smq[i]; }
        float mu = S * (1.0f/DMM);
        float var = Q * (1.0f/DMM) - mu*mu;
        mu_s = mu;
        rs_s = rsqrtf(var + 1e-5f);
    }
    __syncthreads();
    float mu = mu_s, rs = rs_s;
    float* yr = y + (size_t)row*DMM;
#pragma unroll
    for (int i = 0; i < 3; i++) {
        int d = threadIdx.x + 256*i;
        yr[d] = (v[i]-mu)*rs*w[d] + b[d];
    }
}

// -------------------- tensor-core tf32 GEMM, cp.async 4-stage, no-cvt ------
// SPLIT: blockIdx.z slices K (kSlice each); raw partials to part + z*M*ldc.
template<int BN, int ACT, bool HAS_BIAS, bool HAS_RES, bool SPLIT>
__global__ __launch_bounds__(256, 2) void gemm_tc(
    const float* __restrict__ A, int lda,
    const float* __restrict__ Bw, int ldb,     // (N, K) row-major
    const float* __restrict__ bias,
    const float* res,
    float* C, int ldc,
    int M, int N, int Kd, int kSlice,
    float* part)
{
    const int BM = 128, SK = 20, STG = 4;
    const int WC = (BN == 128) ? 4 : 2;
    const int WARP_M = (BN == 128) ? 64 : 32;
    const int MT = WARP_M / 16;
    const int NT = 4;

    extern __shared__ float sm[];
    float* As = sm;
    float* Bs = sm + STG*BM*SK;

    int tid  = threadIdx.x;
    int wid  = tid >> 5;
    int lane = tid & 31;
    int g    = lane >> 2;
    int tg   = lane & 3;
    int wm = (wid / WC) * WARP_M;
    int wn = (wid % WC) * 32;
    int m0 = blockIdx.y * BM;
    int n0 = blockIdx.x * BN;
    int kBegin = SPLIT ? blockIdx.z * kSlice : 0;
    int kCount = SPLIT ? kSlice : Kd;

    float acc[MT][NT][4];
#pragma unroll
    for (int i = 0; i < MT; i++)
#pragma unroll
        for (int j = 0; j < NT; j++)
#pragma unroll
            for (int q = 0; q < 4; q++) acc[i][j][q] = 0.f;

    auto stageLoad = [&](int k0, int buf) {
        float* Asb = As + buf*BM*SK;
        float* Bsb = Bs + buf*BN*SK;
#pragma unroll
        for (int q = 0; q < 2; q++) {
            int f = tid + q*256;
            int m = f >> 2, kv = (f & 3) * 4;
            cp_async16((uint32_t)__cvta_generic_to_shared(Asb + m*SK + kv),
                       A + (size_t)(m0+m)*lda + k0 + kv);
        }
#pragma unroll
        for (int q = 0; q < BN/64; q++) {
            int f = tid + q*256;
            int n = f >> 2, kv = (f & 3) * 4;
            cp_async16((uint32_t)__cvta_generic_to_shared(Bsb + n*SK + kv),
                       Bw + (size_t)(n0+n)*ldb + k0 + kv);
        }
    };

    int nIter = kCount / 16;   // >= 3 at all call sites
    stageLoad(kBegin, 0);      cp_commit();
    stageLoad(kBegin + 16, 1); cp_commit();
    stageLoad(kBegin + 32, 2); cp_commit();

    for (int it = 0; it < nIter; it++) {
        cp_wait<2>();
        __syncthreads();

        int buf = it & 3;
        const float* Asb = As + buf*BM*SK;
        const float* Bsb = Bs + buf*BN*SK;
#pragma unroll
        for (int kk = 0; kk < 2; kk++) {
            int kb = kk*8;
            uint32_t bf[NT][2];
#pragma unroll
            for (int tn = 0; tn < NT; tn++) {
                int n = wn + tn*8 + g;
                bf[tn][0] = __float_as_uint(Bsb[n*SK + kb + tg]);
                bf[tn][1] = __float_as_uint(Bsb[n*SK + kb + tg + 4]);
            }
#pragma unroll
            for (int tm = 0; tm < MT; tm++) {
                int r = wm + tm*16 + g;
                uint32_t af[4];
                af[0] = __float_as_uint(Asb[(r    )*SK + kb + tg    ]);
                af[1] = __float_as_uint(Asb[(r + 8)*SK + kb + tg    ]);
                af[2] = __float_as_uint(Asb[(r    )*SK + kb + tg + 4]);
                af[3] = __float_as_uint(Asb[(r + 8)*SK + kb + tg + 4]);
#pragma unroll
                for (int tn = 0; tn < NT; tn++)
                    mma_tf32(acc[tm][tn], af, bf[tn]);
            }
        }

        int nxt = it + 3;
        if (nxt < nIter) stageLoad(kBegin + nxt*16, nxt & 3);
        cp_commit();
    }

    // epilogue
    float* outp = SPLIT ? (part + (size_t)blockIdx.z * M * ldc) : C;
#pragma unroll
    for (int tm = 0; tm < MT; tm++) {
        int mrow = m0 + wm + tm*16 + g;
#pragma unroll
        for (int tn = 0; tn < NT; tn++) {
            int ncol = n0 + wn + tn*8 + 2*tg;
            float v0 = acc[tm][tn][0];
            float v1 = acc[tm][tn][1];
            float v2 = acc[tm][tn][2];
            float v3 = acc[tm][tn][3];
            size_t o0 = (size_t)mrow*ldc + ncol;
            size_t o1 = (size_t)(mrow+8)*ldc + ncol;
            if (!SPLIT) {
                if (HAS_BIAS) {
                    float b0v = bias[ncol], b1v = bias[ncol+1];
                    v0 += b0v; v1 += b1v; v2 += b0v; v3 += b1v;
                }
                if (ACT == 1) {
                    v0 = gelu_exact(v0); v1 = gelu_exact(v1);
                    v2 = gelu_exact(v2); v3 = gelu_exact(v3);
                } else if (ACT == 2) {
                    v0 = (v0 > 20.f) ? v0 : log1pf(__expf(v0));
                    v1 = (v1 > 20.f) ? v1 : log1pf(__expf(v1));
                    v2 = (v2 > 20.f) ? v2 : log1pf(__expf(v2));
                    v3 = (v3 > 20.f) ? v3 : log1pf(__expf(v3));
                }
                if (HAS_RES) {
                    float2 r0 = *reinterpret_cast<const float2*>(res + o0);
                    float2 r1 = *reinterpret_cast<const float2*>(res + o1);
                    v0 += r0.x; v1 += r0.y; v2 += r1.x; v3 += r1.y;
                }
            }
            *reinterpret_cast<float2*>(outp + o0) = make_float2(v0, v1);
            *reinterpret_cast<float2*>(outp + o1) = make_float2(v2, v3);
        }
    }
}

// reduce split-K partials
__global__ void reduce_splitk(const float* __restrict__ part, float* __restrict__ out, int MN) {
    int i = blockIdx.x*256 + threadIdx.x;
    if (i >= MN) return;
    float s = 0.f;
#pragma unroll
    for (int k = 0; k < XSPLIT; k++) s += part[(size_t)k*MN + i];
    out[i] = s;
}

// -------------------- causal depthwise conv (K=4) + silu (scalar, proven) --------
__global__ void conv_silu_kernel(const float* __restrict__ xz,
                                 const float* __restrict__ cw,
                                 const float* __restrict__ cb,
                                 float* __restrict__ xc) {
    int idx = blockIdx.x * blockDim.x + threadIdx.x;
    if (idx >= RTOT*DII) return;
    int d = idx % DII;
    int r = idx / DII;
    int s = r & (SS-1);
    float acc = cb[d];
#pragma unroll
    for (int k = 0; k < KKC; k++) {
        int sk = s - (KKC-1) + k;
        if (sk >= 0)
            acc = fmaf(xz[(size_t)(r + sk - s)*(2*DII) + d], cw[d*KKC + k], acc);
    }
    float sg = 1.f / (1.f + __expf(-acc));
    xc[idx] = acc * sg;
}

// -------------------- selective scan: double-buffered cp.async + power-tree --------
__global__ __launch_bounds__(128) void scan_kernel(
    const float* __restrict__ delta, const float* __restrict__ dbc,
    const float* __restrict__ xc,    const float* __restrict__ xz,
    const float* __restrict__ A_log, const float* __restrict__ Dw,
    float* __restrict__ y)
{
    const int ST = 8;
    int b  = blockIdx.y;
    int d0 = blockIdx.x*128;
    int d  = d0 + threadIdx.x;
    int tid = threadIdx.x;

    float Av[DSS];
#pragma unroll
    for (int i = 0; i < DSS; i++) Av[i] = -__expf(A_log[d*DSS + i]);
    float a0 = Av[0];
    bool fast = true;
#pragma unroll
    for (int i = 0; i < DSS; i++)
        if (fabsf(Av[i] - (float)(i+1)*a0) > 1e-4f*fabsf(Av[i]) + 1e-6f) fast = false;

    float Dd = Dw[d];
    float h[DSS];
#pragma unroll
    for (int i = 0; i < DSS; i++) h[i] = 0.f;

    __shared__ float sDL[2][ST][128];
    __shared__ float sU [2][ST][128];
    __shared__ float sZ [2][ST][128];
    __shared__ float sBC[2][ST][32];

    size_t rBase = (size_t)b*SS;

    auto stage = [&](int blk, int buf) {
        int s0 = blk*ST;
#pragma unroll
        for (int q = 0; q < 2; q++) {
            int f = tid + q*128;
            int j = f >> 5, c4 = (f & 31)*4;
            size_t row = rBase + s0 + j;
            cp_async16((uint32_t)__cvta_generic_to_shared(&sDL[buf][j][c4]),
                       delta + row*DII + d0 + c4);
            cp_async16((uint32_t)__cvta_generic_to_shared(&sU[buf][j][c4]),
                       xc + row*DII + d0 + c4);
            cp_async16((uint32_t)__cvta_generic_to_shared(&sZ[buf][j][c4]),
                       xz + row*2*DII + DII + d0 + c4);
        }
        if (tid < ST*8) {
            int j = tid >> 3, c4 = (tid & 7)*4;
            cp_async16((uint32_t)__cvta_generic_to_shared(&sBC[buf][j][c4]),
                       dbc + (rBase + j + s0)*DBCP + DTRR + c4);
        }
    };

    const int nBlk = SS/ST;   // 64
    stage(0, 0);
    cp_commit();

    for (int blk = 0; blk < nBlk; blk++) {
        int buf = blk & 1;
        cp_wait<0>();
        __syncthreads();
        if (blk + 1 < nBlk) stage(blk + 1, buf ^ 1);
        cp_commit();

        int s0 = blk*ST;
#pragma unroll
        for (int j = 0; j < ST; j++) {
            float dl = sDL[buf][j][tid];
            float u  = sU [buf][j][tid];
            float z  = sZ [buf][j][tid];
            float du = dl*u;
            float yacc = 0.f;
            if (fast) {
                float t  = __expf(dl*a0);
                float t2 = t*t;
                float t3 = t2*t;
                float t4 = t2*t2;
                float pk = 1.f;
#pragma unroll
                for (int k = 0; k < 4; k++) {
                    float e0 = pk*t, e1 = pk*t2, e2 = pk*t3, e3 = pk*t4;
                    int i0 = k*4;
                    h[i0+0] = fmaf(h[i0+0], e0, du*sBC[buf][j][i0+0]);
                    yacc = fmaf(h[i0+0], sBC[buf][j][16+i0+0], yacc);
                    h[i0+1] = fmaf(h[i0+1], e1, du*sBC[buf][j][i0+1]);
                    yacc = fmaf(h[i0+1], sBC[buf][j][16+i0+1], yacc);
                    h[i0+2] = fmaf(h[i0+2], e2, du*sBC[buf][j][i0+2]);
                    yacc = fmaf(h[i0+2], sBC[buf][j][16+i0+2], yacc);
                    h[i0+3] = fmaf(h[i0+3], e3, du*sBC[buf][j][i0+3]);
                    yacc = fmaf(h[i0+3], sBC[buf][j][16+i0+3], yacc);
                    pk = e3;
                }
            } else {
#pragma unroll
                for (int i = 0; i < DSS; i++) {
                    float e = __expf(dl*Av[i]);
                    h[i] = fmaf(h[i], e, du*sBC[buf][j][i]);
                    yacc = fmaf(h[i], sBC[buf][j][16+i], yacc);
                }
            }
            float ys = yacc + u*Dd;
            float sg = 1.f / (1.f + __expf(-z));
            y[(rBase + s0 + j)*DII + d] = ys * (z*sg);
        }
    }
}

// -------------------- final LN + head --------------------
__global__ __launch_bounds__(256) void headrow_kernel(const float* __restrict__ x,
                                                      const float* __restrict__ w,
                                                      const float* __restrict__ b,
                                                      const float* __restrict__ wh,
                                                      float* __restrict__ rowdot) {
    int row = blockIdx.x;
    const float* xr = x + (size_t)row*DMM;
    float v[3];
    float s = 0.f, sq = 0.f;
#pragma unroll
    for (int i = 0; i < 3; i++) {
        v[i] = xr[threadIdx.x + 256*i];
        s += v[i]; sq += v[i]*v[i];
    }
    __shared__ float sms[8], smq[8];
    __shared__ float mu_s, rs_s;
#pragma unroll
    for (int o = 16; o > 0; o >>= 1) {
        s  += __shfl_xor_sync(0xffffffffu, s,  o);
        sq += __shfl_xor_sync(0xffffffffu, sq, o);
    }
    int lane = threadIdx.x & 31, wid = threadIdx.x >> 5;
    if (lane == 0) { sms[wid] = s; smq[wid] = sq; }
    __syncthreads();
    if (threadIdx.x == 0) {
        float S = 0.f, Q = 0.f;
        for (int i = 0; i < 8; i++) { S += sms[i]; Q += smq[i]; }
        float mu = S * (1.0f/DMM);
        float var = Q * (1.0f/DMM) - mu*mu;
        mu_s = mu; rs_s = rsqrtf(var + 1e-5f);
    }
    __syncthreads();
    float mu = mu_s, rs = rs_s;
    float p = 0.f;
#pragma unroll
    for (int i = 0; i < 3; i++) {
        int d = threadIdx.x + 256*i;
        p = fmaf((v[i]-mu)*rs*w[d] + b[d], wh[d], p);
    }
#pragma unroll
    for (int o = 16; o > 0; o >>= 1) p += __shfl_xor_sync(0xffffffffu, p, o);
    __syncthreads();
    if (lane == 0) sms[wid] = p;
    __syncthreads();
    if (threadIdx.x == 0) {
        float S = 0.f;
        for (int i = 0; i < 8; i++) S += sms[i];
        rowdot[row] = S;
    }
}

__global__ __launch_bounds__(256) void final_kernel(const float* __restrict__ rowdot,
                                                    const float* __restrict__ b_head,
                                                    float* __restrict__ out) {
    int b = blockIdx.x;
    float s = 0.f;
    for (int j = threadIdx.x; j < SS; j += 256) s += rowdot[b*SS + j];
    __shared__ float sms[8];
#pragma unroll
    for (int o = 16; o > 0; o >>= 1) s += __shfl_xor_sync(0xffffffffu, s, o);
    int lane = threadIdx.x & 31, wid = threadIdx.x >> 5;
    if (lane == 0) sms[wid] = s;
    __syncthreads();
    if (threadIdx.x == 0) {
        float S = 0.f;
        for (int i = 0; i < 8; i++) S += sms[i];
        out[b] = b_head[0] + S * (1.0f/SS);
    }
}

// -------------------- launch --------------------
extern "C" void kernel_launch(void* const* d_in, const int* in_sizes, int n_in,
                              void* d_out, int out_size) {
    const float* x        = (const float*)d_in[0];
    const float* w_in     = (const float*)d_in[1];
    const float* b_in     = (const float*)d_in[2];
    const float* pe       = (const float*)d_in[3];
    const float* ln1_w    = (const float*)d_in[4];
    const float* ln1_b    = (const float*)d_in[5];
    const float* w_inproj = (const float*)d_in[6];
    const float* conv_w   = (const float*)d_in[7];
    const float* conv_b   = (const float*)d_in[8];
    const float* w_xproj  = (const float*)d_in[9];
    const float* w_dt     = (const float*)d_in[10];
    const float* b_dt     = (const float*)d_in[11];
    const float* A_log    = (const float*)d_in[12];
    const float* Dmat     = (const float*)d_in[13];
    const float* w_outproj= (const float*)d_in[14];
    const float* ln2_w    = (const float*)d_in[15];
    const float* ln2_b    = (const float*)d_in[16];
    const float* ff_w1    = (const float*)d_in[17];
    const float* ff_b1    = (const float*)d_in[18];
    const float* ff_w2    = (const float*)d_in[19];
    const float* ff_b2    = (const float*)d_in[20];
    const float* lnf_w    = (const float*)d_in[21];
    const float* lnf_b    = (const float*)d_in[22];
    const float* w_head   = (const float*)d_in[23];
    const float* b_head   = (const float*)d_in[24];
    float* out = (float*)d_out;

    float *h, *xln, *xz, *xc, *dbc, *delta, *y, *part, *wxp, *rowdot;
    cudaGetSymbolAddress((void**)&h,      g_h);
    cudaGetSymbolAddress((void**)&xln,    g_xln);
    cudaGetSymbolAddress((void**)&xz,     g_xz);
    cudaGetSymbolAddress((void**)&xc,     g_xc);
    cudaGetSymbolAddress((void**)&dbc,    g_dbc);
    cudaGetSymbolAddress((void**)&delta,  g_delta);
    cudaGetSymbolAddress((void**)&y,      g_y);
    cudaGetSymbolAddress((void**)&part,   g_part);
    cudaGetSymbolAddress((void**)&wxp,    g_wxp);
    cudaGetSymbolAddress((void**)&rowdot, g_rowdot);

    // dynamic smem: 4 stages * (BM + BN) * 20 floats
    const int SM128 = 4*(128+128)*20*4;   // 81,920 B
    const int SM64  = 4*(128+64)*20*4;    // 61,440 B
    cudaFuncSetAttribute(gemm_tc<128,0,false,false,false>, cudaFuncAttributeMaxDynamicSharedMemorySize, SM128);
    cudaFuncSetAttribute(gemm_tc<128,0,false,false,true>,  cudaFuncAttributeMaxDynamicSharedMemorySize, SM128);
    cudaFuncSetAttribute(gemm_tc<128,1,true,false,false>,  cudaFuncAttributeMaxDynamicSharedMemorySize, SM128);
    cudaFuncSetAttribute(gemm_tc<128,2,true,false,false>,  cudaFuncAttributeMaxDynamicSharedMemorySize, SM128);
    cudaFuncSetAttribute(gemm_tc<64,0,false,true,false>,   cudaFuncAttributeMaxDynamicSharedMemorySize, SM64);
    cudaFuncSetAttribute(gemm_tc<64,0,true,true,false>,    cudaFuncAttributeMaxDynamicSharedMemorySize, SM64);

    const int GM = RTOT/128;  // 16 row-blocks

    // pad xproj weights once per call
    pad_xproj_kernel<<<(LLN*DBCP*DII + 255)/256, 256>>>(w_xproj, wxp);

    embed_kernel<<<(RTOT*DMM + 255)/256, 256>>>(x, w_in, b_in, pe, h);

    for (int l = 0; l < LLN; l++) {
        // ln1
        ln_kernel<<<RTOT, 256>>>(h, ln1_w + l*DMM, ln1_b + l*DMM, xln);
        // inproj: xz[2048,3072] = xln @ w_inproj^T   (TC tf32)
        gemm_tc<128,0,false,false,false><<<dim3((2*DII)/128, GM), 256, SM128>>>(
            xln, DMM, w_inproj + (size_t)l*2*DII*DMM, DMM, nullptr, nullptr,
            xz, 2*DII, RTOT, 2*DII, DMM, 0, nullptr);
        // conv + silu
        conv_silu_kernel<<<(RTOT*DII + 255)/256, 256>>>(
            xz, conv_w + (size_t)l*DII*KKC, conv_b + l*DII, xc);
        // xproj (TC split-K, padded N=128): part = xc @ wxp^T
        gemm_tc<128,0,false,false,true><<<dim3(1, GM, XSPLIT), 256, SM128>>>(
            xc, DII, wxp + (size_t)l*DBCP*DII, DII, nullptr, nullptr,
            nullptr, DBCP, RTOT, DBCP, DII, DII/XSPLIT, part);
        reduce_splitk<<<(RTOT*DBCP + 255)/256, 256>>>(part, dbc, RTOT*DBCP);
        // delta = softplus(dbc[:, :48] @ w_dt^T + b_dt)   (TC tf32, K=48)
        gemm_tc<128,2,true,false,false><<<dim3(DII/128, GM), 256, SM128>>>(
            dbc, DBCP, w_dt + (size_t)l*DII*DTRR, DTRR, b_dt + l*DII, nullptr,
            delta, DII, RTOT, DII, DTRR, 0, nullptr);
        // scan -> y (double-buffered cp.async staging, power-tree)
        scan_kernel<<<dim3(DII/128, BB), 128>>>(
            delta, dbc, xc, xz, A_log + (size_t)l*DII*DSS, Dmat + l*DII, y);
        // h += y @ w_outproj^T   (TC tf32)
        gemm_tc<64,0,false,true,false><<<dim3(DMM/64, GM), 256, SM64>>>(
            y, DII, w_outproj + (size_t)l*DMM*DII, DII, nullptr, h,
            h, DMM, RTOT, DMM, DII, 0, nullptr);
        // ln2
        ln_kernel<<<RTOT, 256>>>(h, ln2_w + l*DMM, ln2_b + l*DMM, xln);
        // ff1: f = gelu(xln @ ff_w1^T + b1)   (TC tf32)
        gemm_tc<128,1,true,false,false><<<dim3((2*DMM)/128, GM), 256, SM128>>>(
            xln, DMM, ff_w1 + (size_t)l*2*DMM*DMM, DMM, ff_b1 + l*2*DMM, nullptr,
            y, 2*DMM, RTOT, 2*DMM, DMM, 0, nullptr);
        // h += f @ ff_w2^T + b2   (TC tf32)
        gemm_tc<64,0,true,true,false><<<dim3(DMM/64, GM), 256, SM64>>>(
            y, 2*DMM, ff_w2 + (size_t)l*DMM*2*DMM, 2*DMM, ff_b2 + l*DMM, h,
            h, DMM, RTOT, DMM, 2*DMM, 0, nullptr);
    }

    headrow_kernel<<<RTOT, 256>>>(h, lnf_w, lnf_b, w_head, rowdot);
    final_kernel<<<BB, 256>>>(rowdot, b_head, out);
}